// round 1
// baseline (speedup 1.0000x reference)
#include <cuda_runtime.h>
#include <cstdint>

// Problem constants (fixed shapes for this problem instance).
static constexpr int       kNumPos = 8192;
static constexpr int       kNumNeg = 4000;
static constexpr long long kNTot   = (long long)kNumPos + (long long)kNumPos * kNumNeg; // 32,776,192

// Count-kernel launch geometry.
static constexpr int NBLK_B  = 304;   // persistent-ish blocks (2x152 SMs)
static constexpr int THR_B   = 192;   // 6 warps
static constexpr int NWARP_B = 6;
static constexpr int SMEM_B  = kNumPos * 4 /*pos*/ + NWARP_B * kNumPos * 4 /*hists*/; // 229376 B

__device__ float    g_pos[kNumPos];
__device__ unsigned g_partial[NBLK_B * kNumPos];
__device__ int      g_is64;

// ---------------------------------------------------------------------------
// Detect index dtype (int64 vs int32) from data. If the buffer is really
// int32, reading it as u64 packs two indices per word -> values >= 2^32 >> kNTot
// with overwhelming probability across 64 samples.
// ---------------------------------------------------------------------------
__global__ void detect_kernel(const unsigned long long* __restrict__ idx) {
    if (threadIdx.x == 0 && blockIdx.x == 0) {
        int is64 = 1;
        for (int i = 0; i < 64; ++i)
            if (idx[i] >= (unsigned long long)kNTot) is64 = 0;
        g_is64 = is64;
    }
}

// ---------------------------------------------------------------------------
// Pass A: scan index, scatter pos values. Also zero out[0] (poisoned by harness).
// ---------------------------------------------------------------------------
__global__ void __launch_bounds__(256) scatter_pos_kernel(
    const void* __restrict__ idx_raw, const float* __restrict__ pred,
    float* __restrict__ out) {
    if (blockIdx.x == 0 && threadIdx.x == 0) out[0] = 0.0f;
    const long long tid    = blockIdx.x * (long long)blockDim.x + threadIdx.x;
    const long long stride = (long long)gridDim.x * blockDim.x;
    if (g_is64) {
        const ulonglong2* idx2 = (const ulonglong2*)idx_raw;
        const long long nvec = kNTot / 2;
        #pragma unroll 4
        for (long long v = tid; v < nvec; v += stride) {
            ulonglong2 iv = idx2[v];
            if (iv.x < (unsigned long long)kNumPos) g_pos[iv.x] = pred[2 * v];
            if (iv.y < (unsigned long long)kNumPos) g_pos[iv.y] = pred[2 * v + 1];
        }
    } else {
        const uint4* idx4 = (const uint4*)idx_raw;
        const long long nvec = kNTot / 4;
        #pragma unroll 4
        for (long long v = tid; v < nvec; v += stride) {
            uint4 iv = idx4[v];
            if (iv.x < (unsigned)kNumPos) g_pos[iv.x] = pred[4 * v];
            if (iv.y < (unsigned)kNumPos) g_pos[iv.y] = pred[4 * v + 1];
            if (iv.z < (unsigned)kNumPos) g_pos[iv.z] = pred[4 * v + 2];
            if (iv.w < (unsigned)kNumPos) g_pos[iv.w] = pred[4 * v + 3];
        }
    }
}

// ---------------------------------------------------------------------------
// Pass B: per-warp smem histograms with __match_any_sync leader aggregation.
// Must be called convergently by all 32 lanes (no surrounding divergence).
// ---------------------------------------------------------------------------
__device__ __forceinline__ void hist_step(unsigned long long i, float val, int lane,
                                          const float* __restrict__ s_pos,
                                          unsigned* __restrict__ myhist) {
    const bool neg = (i >= (unsigned long long)kNumPos);
    const unsigned s = neg ? (unsigned)(i - (unsigned long long)kNumPos) / 4000u : 0u;
    const float p = s_pos[s];                     // safe: s==0 for non-neg lanes
    const bool bit = neg && (val > p);
    const unsigned key = bit ? s : (unsigned)(kNumPos + lane); // unique keys for non-contributors
    const unsigned grp = __match_any_sync(0xffffffffu, key);
    if (bit && lane == (__ffs(grp) - 1)) {
        myhist[s] += (unsigned)__popc(grp);       // leader adds group count, race-free
    }
}

__global__ void __launch_bounds__(THR_B, 1) count_kernel(
    const void* __restrict__ idx_raw, const float* __restrict__ pred) {
    extern __shared__ unsigned char smem_raw[];
    float*    s_pos  = (float*)smem_raw;
    unsigned* s_hist = (unsigned*)(smem_raw + (size_t)kNumPos * 4);
    const int tid  = threadIdx.x;
    const int lane = tid & 31;
    unsigned* myhist = s_hist + (size_t)(tid >> 5) * kNumPos;

    for (int k = tid; k < kNumPos; k += THR_B) s_pos[k] = g_pos[k];
    for (int k = tid; k < NWARP_B * kNumPos; k += THR_B) s_hist[k] = 0u;
    __syncthreads();

    if (g_is64) {
        const ulonglong2* idx2 = (const ulonglong2*)idx_raw;
        const float2*     val2 = (const float2*)pred;
        const long long nvec   = kNTot / 2;
        const long long base   = blockIdx.x * (long long)THR_B + tid;
        const long long stride = (long long)NBLK_B * THR_B;
        const int iters = (int)((nvec + stride - 1) / stride);  // uniform across grid
        #pragma unroll 4
        for (int it = 0; it < iters; ++it) {
            const long long v = base + (long long)it * stride;
            const bool inb = (v < nvec);
            ulonglong2 iv = make_ulonglong2(0ull, 0ull);
            float2     vv = make_float2(0.f, 0.f);
            if (inb) { iv = idx2[v]; vv = val2[v]; }
            hist_step(iv.x, vv.x, lane, s_pos, myhist);
            hist_step(iv.y, vv.y, lane, s_pos, myhist);
        }
    } else {
        const uint4*  idx4 = (const uint4*)idx_raw;
        const float4* val4 = (const float4*)pred;
        const long long nvec   = kNTot / 4;
        const long long base   = blockIdx.x * (long long)THR_B + tid;
        const long long stride = (long long)NBLK_B * THR_B;
        const int iters = (int)((nvec + stride - 1) / stride);
        #pragma unroll 2
        for (int it = 0; it < iters; ++it) {
            const long long v = base + (long long)it * stride;
            const bool inb = (v < nvec);
            uint4  iv = make_uint4(0u, 0u, 0u, 0u);
            float4 vv = make_float4(0.f, 0.f, 0.f, 0.f);
            if (inb) { iv = idx4[v]; vv = val4[v]; }
            hist_step(iv.x, vv.x, lane, s_pos, myhist);
            hist_step(iv.y, vv.y, lane, s_pos, myhist);
            hist_step(iv.z, vv.z, lane, s_pos, myhist);
            hist_step(iv.w, vv.w, lane, s_pos, myhist);
        }
    }
    __syncthreads();

    // Combine the 6 warp histograms and emit one per-block partial (no atomics).
    for (int k = tid; k < kNumPos; k += THR_B) {
        unsigned c = 0;
        #pragma unroll
        for (int w = 0; w < NWARP_B; ++w) c += s_hist[(size_t)w * kNumPos + k];
        g_partial[(size_t)blockIdx.x * kNumPos + k] = c;
    }
}

// ---------------------------------------------------------------------------
// Pass C: reduce partials -> sample_mrr, mean.  out layout: [mrr, sample_mrr[8192]]
// ---------------------------------------------------------------------------
__global__ void __launch_bounds__(256) finalize_kernel(float* __restrict__ out) {
    const int bin = blockIdx.x * blockDim.x + threadIdx.x;  // 8192 threads total
    unsigned c = 0;
    #pragma unroll 4
    for (int b = 0; b < NBLK_B; ++b) c += g_partial[(size_t)b * kNumPos + bin];
    const float mrr_i = 1.0f / (float)(1u + c);
    out[1 + bin] = mrr_i;

    float s = mrr_i;
    #pragma unroll
    for (int o = 16; o; o >>= 1) s += __shfl_down_sync(0xffffffffu, s, o);
    __shared__ float ws[8];
    const int lane = threadIdx.x & 31, warp = threadIdx.x >> 5;
    if (lane == 0) ws[warp] = s;
    __syncthreads();
    if (warp == 0) {
        s = (lane < (int)(blockDim.x >> 5)) ? ws[lane] : 0.0f;
        #pragma unroll
        for (int o = 16; o; o >>= 1) s += __shfl_down_sync(0xffffffffu, s, o);
        if (lane == 0) atomicAdd(out, s * (1.0f / (float)kNumPos));
    }
}

// ---------------------------------------------------------------------------
extern "C" void kernel_launch(void* const* d_in, const int* in_sizes, int n_in,
                              void* d_out, int out_size) {
    const float* pred = (const float*)d_in[0];
    const void*  idx  = (const void*)d_in[1];
    float*       out  = (float*)d_out;

    cudaFuncSetAttribute(count_kernel, cudaFuncAttributeMaxDynamicSharedMemorySize, SMEM_B);

    detect_kernel<<<1, 32>>>((const unsigned long long*)idx);
    scatter_pos_kernel<<<2048, 256>>>(idx, pred, out);
    count_kernel<<<NBLK_B, THR_B, SMEM_B>>>(idx, pred);
    finalize_kernel<<<kNumPos / 256, 256>>>(out);
}

// round 2
// speedup vs baseline: 2.5954x; 2.5954x over previous
#include <cuda_runtime.h>
#include <cstdint>

// Problem constants (fixed shapes for this problem instance).
static constexpr int       kNumPos = 8192;
static constexpr int       kNumNeg = 4000;
static constexpr long long kNTot   = (long long)kNumPos + (long long)kNumPos * kNumNeg; // 32,776,192

// Count-kernel geometry: one wave of 152 CTAs, 8 warps each.
static constexpr int NBLK_B  = 152;
static constexpr int THR_B   = 256;
static constexpr int NWARP_B = 8;
// smem: 32KB pos (f32) + 8 warps * 8192 bins * u16 = 128KB  => 160KB total, 1 CTA/SM
static constexpr int SMEM_B  = kNumPos * 4 + NWARP_B * kNumPos * 2;

__device__ float    g_pos[kNumPos];
__device__ unsigned g_partial[NBLK_B * kNumPos];
__device__ int      g_is64;

// ---------------------------------------------------------------------------
// Detect index dtype (int64 vs int32) from data. int32 data read as u64 packs
// two indices -> values >= 2^32 >> kNTot with overwhelming probability.
// ---------------------------------------------------------------------------
__global__ void detect_kernel(const unsigned long long* __restrict__ idx) {
    if (threadIdx.x == 0 && blockIdx.x == 0) {
        int is64 = 1;
        #pragma unroll
        for (int i = 0; i < 64; ++i)
            if (idx[i] >= (unsigned long long)kNTot) is64 = 0;
        g_is64 = is64;
    }
}

// ---------------------------------------------------------------------------
// Pass A: scan index, scatter pos values. Also zero out[0] (poisoned).
// ---------------------------------------------------------------------------
__global__ void __launch_bounds__(256) scatter_pos_kernel(
    const void* __restrict__ idx_raw, const float* __restrict__ pred,
    float* __restrict__ out) {
    if (blockIdx.x == 0 && threadIdx.x == 0) out[0] = 0.0f;
    const long long tid    = blockIdx.x * (long long)blockDim.x + threadIdx.x;
    const long long stride = (long long)gridDim.x * blockDim.x;
    if (g_is64) {
        const ulonglong2* idx2 = (const ulonglong2*)idx_raw;
        const long long nvec = kNTot / 2;
        #pragma unroll 4
        for (long long v = tid; v < nvec; v += stride) {
            ulonglong2 iv = idx2[v];
            if (iv.x < (unsigned long long)kNumPos) g_pos[iv.x] = pred[2 * v];
            if (iv.y < (unsigned long long)kNumPos) g_pos[iv.y] = pred[2 * v + 1];
        }
    } else {
        const uint4* idx4 = (const uint4*)idx_raw;
        const long long nvec = kNTot / 4;
        #pragma unroll 4
        for (long long v = tid; v < nvec; v += stride) {
            uint4 iv = idx4[v];
            if (iv.x < (unsigned)kNumPos) g_pos[iv.x] = pred[4 * v];
            if (iv.y < (unsigned)kNumPos) g_pos[iv.y] = pred[4 * v + 1];
            if (iv.z < (unsigned)kNumPos) g_pos[iv.z] = pred[4 * v + 2];
            if (iv.w < (unsigned)kNumPos) g_pos[iv.w] = pred[4 * v + 3];
        }
    }
}

// ---------------------------------------------------------------------------
// Pass B: per-warp u16 smem histograms; __match_any_sync leader aggregation
// makes same-bin collisions within a warp race-free. u16 is safe: a bin's
// global count is bounded by kNumNeg = 4000 < 65535.
// Must be called convergently by all 32 lanes.
// ---------------------------------------------------------------------------
__device__ __forceinline__ void hist_step(unsigned long long i, float val, int lane,
                                          const float* __restrict__ s_pos,
                                          unsigned short* __restrict__ myhist) {
    const bool neg = (i >= (unsigned long long)kNumPos);
    const unsigned s = neg ? (unsigned)(i - (unsigned long long)kNumPos) / 4000u : 0u;
    const float p = s_pos[s];                       // safe: s==0 for non-neg lanes
    const bool bit = neg && (val > p);
    const unsigned key = bit ? s : (unsigned)(kNumPos + lane); // unique keys otherwise
    const unsigned grp = __match_any_sync(0xffffffffu, key);
    if (bit && lane == (__ffs(grp) - 1)) {
        myhist[s] = (unsigned short)(myhist[s] + (unsigned)__popc(grp));
    }
}

__global__ void __launch_bounds__(THR_B, 1) count_kernel(
    const void* __restrict__ idx_raw, const float* __restrict__ pred) {
    extern __shared__ unsigned char smem_raw[];
    float*          s_pos  = (float*)smem_raw;
    unsigned short* s_hist = (unsigned short*)(smem_raw + (size_t)kNumPos * 4);
    const int tid  = threadIdx.x;
    const int lane = tid & 31;
    unsigned short* myhist = s_hist + (size_t)(tid >> 5) * kNumPos;

    for (int k = tid; k < kNumPos; k += THR_B) s_pos[k] = g_pos[k];
    // zero hists as 32-bit words: 8*8192*2/4 = 32768 words
    unsigned* s_hist32 = (unsigned*)s_hist;
    for (int k = tid; k < NWARP_B * kNumPos / 2; k += THR_B) s_hist32[k] = 0u;
    __syncthreads();

    if (g_is64) {
        constexpr int U = 8;                           // 16 elements/thread/stage
        const ulonglong2* idx2 = (const ulonglong2*)idx_raw;
        const float2*     val2 = (const float2*)pred;
        const long long nvec      = kNTot / 2;         // 16,388,096
        const long long stride    = (long long)NBLK_B * THR_B;
        const long long bigstride = stride * U;
        const long long base      = blockIdx.x * (long long)THR_B + tid;
        const int iters = (int)((nvec + bigstride - 1) / bigstride);   // uniform
        for (int it = 0; it < iters; ++it) {
            ulonglong2 iv[U];
            float2     vv[U];
            // front-batched loads: all independent -> high MLP
            #pragma unroll
            for (int u = 0; u < U; ++u) {
                const long long v = base + (long long)it * bigstride + (long long)u * stride;
                iv[u] = make_ulonglong2(0ull, 0ull);
                vv[u] = make_float2(0.f, 0.f);
                if (v < nvec) { iv[u] = idx2[v]; vv[u] = val2[v]; }
            }
            #pragma unroll
            for (int u = 0; u < U; ++u) {
                hist_step(iv[u].x, vv[u].x, lane, s_pos, myhist);
                hist_step(iv[u].y, vv[u].y, lane, s_pos, myhist);
            }
        }
    } else {
        constexpr int U = 8;                           // 32 elements/thread/stage
        const uint4*  idx4 = (const uint4*)idx_raw;
        const float4* val4 = (const float4*)pred;
        const long long nvec      = kNTot / 4;         // 8,194,048
        const long long stride    = (long long)NBLK_B * THR_B;
        const long long bigstride = stride * U;
        const long long base      = blockIdx.x * (long long)THR_B + tid;
        const int iters = (int)((nvec + bigstride - 1) / bigstride);   // uniform
        for (int it = 0; it < iters; ++it) {
            uint4  iv[U];
            float4 vv[U];
            #pragma unroll
            for (int u = 0; u < U; ++u) {
                const long long v = base + (long long)it * bigstride + (long long)u * stride;
                iv[u] = make_uint4(0u, 0u, 0u, 0u);
                vv[u] = make_float4(0.f, 0.f, 0.f, 0.f);
                if (v < nvec) { iv[u] = idx4[v]; vv[u] = val4[v]; }
            }
            #pragma unroll
            for (int u = 0; u < U; ++u) {
                hist_step(iv[u].x, vv[u].x, lane, s_pos, myhist);
                hist_step(iv[u].y, vv[u].y, lane, s_pos, myhist);
                hist_step(iv[u].z, vv[u].z, lane, s_pos, myhist);
                hist_step(iv[u].w, vv[u].w, lane, s_pos, myhist);
            }
        }
    }
    __syncthreads();

    // Combine 8 warp histograms; one per-block u32 partial per bin (no atomics).
    for (int k = tid; k < kNumPos; k += THR_B) {
        unsigned c = 0;
        #pragma unroll
        for (int w = 0; w < NWARP_B; ++w) c += s_hist[(size_t)w * kNumPos + k];
        g_partial[(size_t)blockIdx.x * kNumPos + k] = c;
    }
}

// ---------------------------------------------------------------------------
// Pass C: 256 blocks x 256 threads; each block reduces 32 bins, threads split
// the 152 partials into 8 chunks of 19. Coalesced, high-MLP.
// out layout: [mrr, sample_mrr[8192]]
// ---------------------------------------------------------------------------
__global__ void __launch_bounds__(256) finalize_kernel(float* __restrict__ out) {
    const int tid   = threadIdx.x;
    const int bsub  = tid & 31;            // bin within block
    const int chunk = tid >> 5;            // 0..7
    const int bin   = blockIdx.x * 32 + bsub;

    unsigned c = 0;
    #pragma unroll
    for (int b = chunk; b < NBLK_B; b += 8)
        c += g_partial[(size_t)b * kNumPos + bin];

    __shared__ unsigned sc[256];
    sc[tid] = c;
    __syncthreads();

    if (chunk == 0) {
        unsigned tot = c;
        #pragma unroll
        for (int w = 1; w < 8; ++w) tot += sc[w * 32 + bsub];
        const float mrr_i = 1.0f / (float)(1u + tot);
        out[1 + bin] = mrr_i;

        float s = mrr_i;
        #pragma unroll
        for (int o = 16; o; o >>= 1) s += __shfl_down_sync(0xffffffffu, s, o);
        if (bsub == 0) atomicAdd(out, s * (1.0f / (float)kNumPos));
    }
}

// ---------------------------------------------------------------------------
extern "C" void kernel_launch(void* const* d_in, const int* in_sizes, int n_in,
                              void* d_out, int out_size) {
    const float* pred = (const float*)d_in[0];
    const void*  idx  = (const void*)d_in[1];
    float*       out  = (float*)d_out;

    cudaFuncSetAttribute(count_kernel, cudaFuncAttributeMaxDynamicSharedMemorySize, SMEM_B);

    detect_kernel<<<1, 32>>>((const unsigned long long*)idx);
    scatter_pos_kernel<<<2048, 256>>>(idx, pred, out);
    count_kernel<<<NBLK_B, THR_B, SMEM_B>>>(idx, pred);
    finalize_kernel<<<kNumPos / 32, 256>>>(out);
}